// round 10
// baseline (speedup 1.0000x reference)
#include <cuda_runtime.h>
#include <cuda_bf16.h>
#include <cstdint>

// Problem constants
#define BB 4
#define TT 4096
#define DD 1024
#define HH 16
#define HD 64
#define MM (BB*TT)     // 16384 rows

// ---------------- scratch (device globals; no allocation allowed) ----------
__device__ float g_q[(size_t)BB*HH*TT*HD];     // (b,h,t,e)  64 MB
__device__ float g_k[(size_t)BB*HH*TT*HD];     // (b,h,t,e)  64 MB
__device__ float g_v[(size_t)BB*HH*TT*HD];     // (b,h,t,e)  64 MB
__device__ float g_attn[(size_t)MM*DD];        // (b,t,d)    64 MB
__device__ float g_kv[BB*HH*HD*HD];            // 1 MB
__device__ float g_ksum[BB*HH*HD];             // 16 KB

// ---------------------------------------------------------------------------
// base-PTX building blocks (sm_75/sm_80 -- valid on plain sm_100 target)
// ---------------------------------------------------------------------------
__device__ __forceinline__ void mma_bf16(float* c, const uint32_t* a, const uint32_t* b) {
    asm volatile(
        "mma.sync.aligned.m16n8k16.row.col.f32.bf16.bf16.f32 "
        "{%0,%1,%2,%3}, {%4,%5,%6,%7}, {%8,%9}, {%0,%1,%2,%3};"
        : "+f"(c[0]), "+f"(c[1]), "+f"(c[2]), "+f"(c[3])
        : "r"(a[0]), "r"(a[1]), "r"(a[2]), "r"(a[3]), "r"(b[0]), "r"(b[1]));
}
__device__ __forceinline__ void ldm_x4(uint32_t* r, uint32_t a) {
    asm volatile("ldmatrix.sync.aligned.m8n8.x4.shared.b16 {%0,%1,%2,%3}, [%4];"
        : "=r"(r[0]), "=r"(r[1]), "=r"(r[2]), "=r"(r[3]) : "r"(a));
}
// NON-trans x2: B stored [n][k] with k contiguous -> lane gets (ko=lane&3, n=lane>>2)
__device__ __forceinline__ void ldm_x2(uint32_t* r, uint32_t a) {
    asm volatile("ldmatrix.sync.aligned.m8n8.x2.shared.b16 {%0,%1}, [%2];"
        : "=r"(r[0]), "=r"(r[1]) : "r"(a));
}
__device__ __forceinline__ uint32_t smem_u32(const void* p) {
    uint32_t a;
    asm("{ .reg .u64 t; cvta.to.shared.u64 t, %1; cvt.u32.u64 %0, t; }"
        : "=r"(a) : "l"(p));
    return a;
}

// split float4 -> bf16 hi + bf16 lo, packed 2-per-u32 (low half = even elem)
__device__ __forceinline__ void cvt_pair(float4 v, uint2& hi, uint2& lo) {
    __nv_bfloat16 h0 = __float2bfloat16(v.x), h1 = __float2bfloat16(v.y);
    __nv_bfloat16 h2 = __float2bfloat16(v.z), h3 = __float2bfloat16(v.w);
    __nv_bfloat16 l0 = __float2bfloat16(v.x - __bfloat162float(h0));
    __nv_bfloat16 l1 = __float2bfloat16(v.y - __bfloat162float(h1));
    __nv_bfloat16 l2 = __float2bfloat16(v.z - __bfloat162float(h2));
    __nv_bfloat16 l3 = __float2bfloat16(v.w - __bfloat162float(h3));
    hi.x = (uint32_t)__bfloat16_as_ushort(h0) | ((uint32_t)__bfloat16_as_ushort(h1) << 16);
    hi.y = (uint32_t)__bfloat16_as_ushort(h2) | ((uint32_t)__bfloat16_as_ushort(h3) << 16);
    lo.x = (uint32_t)__bfloat16_as_ushort(l0) | ((uint32_t)__bfloat16_as_ushort(l1) << 16);
    lo.y = (uint32_t)__bfloat16_as_ushort(l2) | ((uint32_t)__bfloat16_as_ushort(l3) << 16);
}

#define RW    12                 // u32 per smem row (48 B; conflict-free for ldmatrix)
#define TIL   (128*RW)           // one 128x16-bf16 tile (6144 B)
#define BUFU  (4*TIL)            // Ahi, Alo, Bhi, Blo per stage (24576 B)
// two stages = 49152 B = 48 KB static smem exactly

// store one K-chunk (16 cols) of A and B, split hi/lo, into a stage buffer
__device__ __forceinline__ void store_chunk(uint32_t* base, int tid,
                                            const float4* pa, const float4* pb) {
    #pragma unroll
    for (int l = 0; l < 2; l++) {
        int f = tid + l * 256;            // float4 id 0..511
        int row = f >> 2;                 // 0..127
        int c4  = (f & 3) << 2;           // float col 0,4,8,12
        int idx = row * RW + (c4 >> 1);
        uint2 hi, lo;
        cvt_pair(pa[l], hi, lo);
        *(uint2*)(base + idx)           = hi;
        *(uint2*)(base + TIL + idx)     = lo;
        cvt_pair(pb[l], hi, lo);
        *(uint2*)(base + 2 * TIL + idx) = hi;
        *(uint2*)(base + 3 * TIL + idx) = lo;
    }
}

// ---------------------------------------------------------------------------
// C = A(MxK) * W^T via 3x-bf16-split mma.sync; tile 128x128, K-chunk 16,
// double-buffered (one __syncthreads per chunk), ldmatrix fragment loads.
// EPI: 0 plain->d_out, 1 phi->g_q, 2 phi*mask->g_k, 3 *mask->g_v
// ---------------------------------------------------------------------------
template<int EPI>
__global__ __launch_bounds__(256, 1)
void sgemm_mma(const float* __restrict__ Ax, const float* __restrict__ W,
               const int* __restrict__ mask, float* __restrict__ outp)
{
    __shared__ __align__(16) uint32_t smu[2 * BUFU];
    const int tid  = threadIdx.x;
    const int wid  = tid >> 5, lane = tid & 31;
    const int g    = lane >> 2, q = lane & 3;
    const int m0   = blockIdx.y * 128;
    const int n0   = blockIdx.x * 128;
    const int wr   = (wid >> 2) * 64;
    const int wc   = (wid & 3) * 32;

    const float* A = (EPI == 0) ? (const float*)g_attn : Ax;
    float* out;
    if      (EPI == 0) out = outp;
    else if (EPI == 1) out = g_q;
    else if (EPI == 2) out = g_k;
    else               out = g_v;

    const uint32_t sb = smem_u32(smu);

    // ldmatrix per-lane addressing (byte offsets within a stage buffer)
    const int arow = lane & 15, acol = (lane >> 4) * 4;       // A: m8n8.x4
    const int brow = lane & 7,  bcol = ((lane >> 3) & 1) * 4; // B: m8n8.x2 (non-trans)
    uint32_t aoff[4], boff[4];
    #pragma unroll
    for (int mt = 0; mt < 4; mt++)
        aoff[mt] = (uint32_t)(((wr + mt * 16 + arow) * RW + acol) * 4);
    #pragma unroll
    for (int nt = 0; nt < 4; nt++)
        boff[nt] = (uint32_t)((2 * TIL + (wc + nt * 8 + brow) * RW + bcol) * 4);

    float acc[4][4][4];
    #pragma unroll
    for (int i = 0; i < 4; i++)
        #pragma unroll
        for (int j = 0; j < 4; j++)
            #pragma unroll
            for (int r = 0; r < 4; r++) acc[i][j][r] = 0.f;

    // prologue: chunk 0 -> stage 0
    float4 pa[2], pb[2];
    #pragma unroll
    for (int l = 0; l < 2; l++) {
        int f = tid + l * 256;
        int row = f >> 2, c4 = (f & 3) << 2;
        pa[l] = *(const float4*)(A + (size_t)(m0 + row) * DD + c4);
        pb[l] = *(const float4*)(W + (size_t)(n0 + row) * DD + c4);
    }
    store_chunk(smu, tid, pa, pb);

    for (int kc = 0; kc < 64; kc++) {
        __syncthreads();                        // stage (kc&1) ready for reads
        if (kc < 63) {                          // prefetch chunk kc+1 to regs
            const int k0 = (kc + 1) * 16;
            #pragma unroll
            for (int l = 0; l < 2; l++) {
                int f = tid + l * 256;
                int row = f >> 2, c4 = (f & 3) << 2;
                pa[l] = *(const float4*)(A + (size_t)(m0 + row) * DD + k0 + c4);
                pb[l] = *(const float4*)(W + (size_t)(n0 + row) * DD + k0 + c4);
            }
        }

        const uint32_t bufb = sb + (uint32_t)((kc & 1) * (BUFU * 4));

        uint32_t af[4][4], al[4][4], bfr[4][2], blr[4][2];
        #pragma unroll
        for (int mt = 0; mt < 4; mt++) {
            uint32_t a = bufb + aoff[mt];
            ldm_x4(af[mt], a);
            ldm_x4(al[mt], a + TIL * 4);
        }
        #pragma unroll
        for (int nt = 0; nt < 4; nt++) {
            uint32_t b = bufb + boff[nt];
            ldm_x2(bfr[nt], b);
            ldm_x2(blr[nt], b + TIL * 4);
        }

        #pragma unroll
        for (int mt = 0; mt < 4; mt++)
            #pragma unroll
            for (int nt = 0; nt < 4; nt++)
                mma_bf16(acc[mt][nt], af[mt], bfr[nt]);
        #pragma unroll
        for (int mt = 0; mt < 4; mt++)
            #pragma unroll
            for (int nt = 0; nt < 4; nt++)
                mma_bf16(acc[mt][nt], af[mt], blr[nt]);
        #pragma unroll
        for (int mt = 0; mt < 4; mt++)
            #pragma unroll
            for (int nt = 0; nt < 4; nt++)
                mma_bf16(acc[mt][nt], al[mt], bfr[nt]);

        if (kc < 63)                            // fill the other stage
            store_chunk(smu + ((kc + 1) & 1) * BUFU, tid, pa, pb);
    }

    // ---- fused epilogue ----
    #pragma unroll
    for (int mt = 0; mt < 4; mt++) {
        #pragma unroll
        for (int half = 0; half < 2; half++) {
            const int m = m0 + wr + mt * 16 + half * 8 + g;
            float mz = 1.f;
            if (EPI == 2 || EPI == 3) mz = (mask[m] != 0) ? 0.f : 1.f;
            const int b_ = m >> 12;
            const int t  = m & (TT - 1);
            #pragma unroll
            for (int nt = 0; nt < 4; nt++) {
                const int c = n0 + wc + nt * 8 + q * 2;
                float v0 = acc[mt][nt][half * 2 + 0];
                float v1 = acc[mt][nt][half * 2 + 1];
                if (EPI == 1 || EPI == 2) {
                    v0 = (v0 > 0.f) ? (v0 + 1.f) : __expf(v0);
                    v1 = (v1 > 0.f) ? (v1 + 1.f) : __expf(v1);
                }
                if (EPI == 2 || EPI == 3) { v0 *= mz; v1 *= mz; }
                float2 w2 = make_float2(v0, v1);
                if (EPI == 0) {
                    *(float2*)(outp + (size_t)m * DD + c) = w2;
                } else {
                    const int h = c >> 6, e = c & 63;
                    *(float2*)(out + (((size_t)(b_ * HH + h)) * TT + t) * HD + e) = w2;
                }
            }
        }
    }
}

// ---------------------------------------------------------------------------
__global__ void zero_kv_kernel()
{
    int i = blockIdx.x * 256 + threadIdx.x;
    if (i < BB * HH * HD * HD) g_kv[i] = 0.f;
    if (i < BB * HH * HD)      g_ksum[i] = 0.f;
}

// ---------------------------------------------------------------------------
#define KV_NCH 8
__global__ __launch_bounds__(128)
void kv_kernel()
{
    const int bh  = blockIdx.x;
    const int ch  = blockIdx.y;
    const int tid = threadIdx.x;
    const int grp = tid >> 6;
    const int gt  = tid & 63;
    const int d0  = (gt >> 3) * 8;
    const int e0  = (gt & 7) * 8;
    const int RPB = TT / KV_NCH;
    const int RPG = RPB / 2;

    const float* kp = g_k + ((size_t)bh * TT + ch * RPB + grp * RPG) * HD;
    const float* vp = g_v + ((size_t)bh * TT + ch * RPB + grp * RPG) * HD;

    __shared__ float ks[2][8][64];
    __shared__ float vs[2][8][64];

    float acc[8][8];
    #pragma unroll
    for (int i = 0; i < 8; i++)
        #pragma unroll
        for (int j = 0; j < 8; j++) acc[i][j] = 0.f;
    float ksacc = 0.f;

    for (int t0 = 0; t0 < RPG; t0 += 8) {
        #pragma unroll
        for (int l = 0; l < 2; l++) {
            int f = gt + l * 64;
            int r = f >> 4, c = (f & 15) * 4;
            *(float4*)&ks[grp][r][c] = *(const float4*)(kp + (size_t)(t0 + r) * HD + c);
            *(float4*)&vs[grp][r][c] = *(const float4*)(vp + (size_t)(t0 + r) * HD + c);
        }
        __syncthreads();
        #pragma unroll
        for (int tt = 0; tt < 8; tt++) {
            float kr[8], vr[8];
            *(float4*)(kr)     = *(const float4*)&ks[grp][tt][d0];
            *(float4*)(kr + 4) = *(const float4*)&ks[grp][tt][d0 + 4];
            *(float4*)(vr)     = *(const float4*)&vs[grp][tt][e0];
            *(float4*)(vr + 4) = *(const float4*)&vs[grp][tt][e0 + 4];
            #pragma unroll
            for (int i = 0; i < 8; i++)
                #pragma unroll
                for (int j = 0; j < 8; j++) acc[i][j] += kr[i] * vr[j];
            ksacc += ks[grp][tt][gt];
        }
        __syncthreads();
    }

    float* kvp = g_kv + (size_t)bh * HD * HD;
    #pragma unroll
    for (int i = 0; i < 8; i++)
        #pragma unroll
        for (int j = 0; j < 8; j++)
            atomicAdd(&kvp[(d0 + i) * HD + e0 + j], acc[i][j]);
    atomicAdd(&g_ksum[bh * HD + gt], ksacc);
}

// ---------------------------------------------------------------------------
__global__ __launch_bounds__(256)
void out_kernel()
{
    const int bh  = blockIdx.y;
    const int t0  = blockIdx.x * 128;
    const int tid = threadIdx.x;

    __shared__ float kvs[64][64];
    __shared__ float kss[64];

    const float* kvp = g_kv + (size_t)bh * HD * HD;
    #pragma unroll
    for (int l = 0; l < 4; l++) {
        int f = tid + l * 256;
        int r = f >> 4, c = (f & 15) * 4;
        *(float4*)&kvs[r][c] = *(const float4*)(kvp + r * HD + c);
    }
    if (tid < 64) kss[tid] = g_ksum[bh * HD + tid];
    __syncthreads();

    const int row = tid >> 1;
    const int c0  = (tid & 1) * 32;
    const float* qp = g_q + ((size_t)bh * TT + t0 + row) * HD;

    float acc[32];
    #pragma unroll
    for (int j = 0; j < 32; j++) acc[j] = 0.f;
    float norm = 0.f;

    #pragma unroll
    for (int dq = 0; dq < 64; dq += 4) {
        float4 q4 = *(const float4*)(qp + dq);
        float qa[4] = {q4.x, q4.y, q4.z, q4.w};
        #pragma unroll
        for (int s = 0; s < 4; s++) {
            int d = dq + s;
            norm += qa[s] * kss[d];
            #pragma unroll
            for (int j = 0; j < 32; j++) acc[j] += qa[s] * kvs[d][c0 + j];
        }
    }

    float inv = 1.f / fmaxf(norm, 1e-6f);
    const int b_ = bh >> 4, h = bh & 15;
    float* op = g_attn + ((size_t)b_ * TT + t0 + row) * DD + h * HD + c0;
    #pragma unroll
    for (int j = 0; j < 32; j++) op[j] = acc[j] * inv;
}

// ---------------------------------------------------------------------------
extern "C" void kernel_launch(void* const* d_in, const int* in_sizes, int n_in,
                              void* d_out, int out_size)
{
    const float* x  = (const float*)d_in[0];
    const int*   mk = (const int*)d_in[1];       // bool mask promoted to int32
    const float* Wq = (const float*)d_in[2];
    const float* Wk = (const float*)d_in[3];
    const float* Wv = (const float*)d_in[4];
    const float* Wo = (const float*)d_in[5];
    float* out      = (float*)d_out;

    dim3 gg(DD / 128, MM / 128);   // (8, 128): x = n-tile fastest -> A-stripe L2 reuse

    sgemm_mma<1><<<gg, 256>>>(x, Wq, mk, nullptr);   // q = phi(x Wq^T)
    sgemm_mma<2><<<gg, 256>>>(x, Wk, mk, nullptr);   // k = phi(x Wk^T)*m
    sgemm_mma<3><<<gg, 256>>>(x, Wv, mk, nullptr);   // v = (x Wv^T)*m

    zero_kv_kernel<<<(BB * HH * HD * HD + 255) / 256, 256>>>();
    kv_kernel<<<dim3(BB * HH, KV_NCH), 128>>>();
    out_kernel<<<dim3(TT / 128, BB * HH), 256>>>();

    sgemm_mma<0><<<gg, 256>>>(nullptr, Wo, mk, out); // y = attn Wo^T
}